// round 9
// baseline (speedup 1.0000x reference)
#include <cuda_runtime.h>
#include <cstdint>

#define Bv 8192
#define Mv 512
#define Ov 128

// ---- smem byte offsets (per CTA, covers 256 rows of one batch) ----
#define SM_XH    0        // x bf16: 256 rows * 128B (chunk-XOR swizzled) = 32768
#define SM_LN    32768    // lam^T bf16 (o-row-permuted): 128 rows * 128B = 16384
#define SM_SRED  49152    // 16 x 64 f32 column-sum partials = 4096
#define SM_SPART 53248    // own s[64] partial  = 256
#define SM_SPEER 53504    // peer s[64] partial (written by peer CTA) = 256
#define SM_POOL  53760    // pooled[128] f32 = 512
#define SMEM_BYTES 54272

__device__ __forceinline__ uint32_t cvta_smem(const void* p) {
    uint32_t a;
    asm("{ .reg .u64 t; cvta.to.shared.u64 t, %1; cvt.u32.u64 %0, t; }" : "=r"(a) : "l"(p));
    return a;
}

__device__ __forceinline__ uint32_t pack_bf16x2(float lo, float hi) {
    uint32_t r;
    asm("cvt.rn.bf16x2.f32 %0, %1, %2;" : "=r"(r) : "f"(hi), "f"(lo));
    return r;
}

__device__ __forceinline__ void ldsm4(uint32_t addr, uint32_t r[4]) {
    asm volatile("ldmatrix.sync.aligned.m8n8.x4.shared.b16 {%0,%1,%2,%3}, [%4];"
        : "=r"(r[0]), "=r"(r[1]), "=r"(r[2]), "=r"(r[3]) : "r"(addr));
}

__device__ __forceinline__ void hmma(float d[4], const uint32_t a[4], const uint32_t b[2]) {
    asm volatile("mma.sync.aligned.m16n8k16.row.col.f32.bf16.bf16.f32 "
        "{%0,%1,%2,%3}, {%4,%5,%6,%7}, {%8,%9}, {%0,%1,%2,%3};"
        : "+f"(d[0]), "+f"(d[1]), "+f"(d[2]), "+f"(d[3])
        : "r"(a[0]), "r"(a[1]), "r"(a[2]), "r"(a[3]), "r"(b[0]), "r"(b[1]));
}

__device__ __forceinline__ float4 ldg_cs4(const float4* p) {
    float4 v;
    asm volatile("ld.global.cs.v4.f32 {%0,%1,%2,%3}, [%4];"
        : "=f"(v.x), "=f"(v.y), "=f"(v.z), "=f"(v.w) : "l"(p));
    return v;
}
__device__ __forceinline__ void stg_cs4(float* p, float a, float b, float c, float d) {
    asm volatile("st.global.cs.v4.f32 [%0], {%1,%2,%3,%4};"
        :: "l"(p), "f"(a), "f"(b), "f"(c), "f"(d) : "memory");
}

extern __shared__ char smem[];

__global__ void __cluster_dims__(2, 1, 1) __launch_bounds__(256, 3)
eq_mma6_kernel(const float* __restrict__ x,
               const float* __restrict__ lam,
               const float* __restrict__ gam,
               float* __restrict__ out)
{
    const uint32_t sb = cvta_smem(smem);
    const int t = threadIdx.x;
    const int b = blockIdx.x >> 1;
    const int rank = blockIdx.x & 1;          // == cluster cta rank
    const int w = t >> 5, lane = t & 31, g = lane >> 2, tg = lane & 3;

    // ---- lam^T -> bf16 smem, o-row-permuted within each 16-row group ----
    {
        const int o = t & 127;
        const int r15 = o & 15;
        const int orow = (o & ~15) | (((r15 & 2) << 2) | ((r15 >> 2) << 1) | (r15 & 1));
        const int q = t >> 7;
        #pragma unroll 4
        for (int j = 0; j < 16; j++) {
            const int fp = q * 16 + j;
            const float v0 = lam[(2 * fp) * Ov + o];
            const float v1 = lam[(2 * fp + 1) * Ov + o];
            const uint32_t h = pack_bf16x2(v0, v1);
            const uint32_t off = (uint32_t)(orow * 128
                + (((fp >> 2) ^ (orow & 7)) << 4) + (fp & 3) * 4);
            *(uint32_t*)(smem + SM_LN + off) = h;
        }
    }

    // ---- x rows [rank*256, rank*256+256): fp32 -> bf16 smem + partial sums ----
    {
        const float4* xg = (const float4*)(x + ((size_t)b * Mv + rank * 256) * 64);
        const int f4 = t & 15, tm = t >> 4;
        const int chunk = f4 >> 1, half = f4 & 1;
        float4 s4 = make_float4(0.f, 0.f, 0.f, 0.f);
        #pragma unroll 4
        for (int i = 0; i < 16; i++) {
            const int m = tm + 16 * i;        // local row 0..255
            const float4 v = ldg_cs4(&xg[m * 16 + f4]);
            s4.x += v.x; s4.y += v.y; s4.z += v.z; s4.w += v.w;
            const uint32_t h01 = pack_bf16x2(v.x, v.y);
            const uint32_t h23 = pack_bf16x2(v.z, v.w);
            const uint32_t off = (uint32_t)(m * 128 + ((chunk ^ (m & 7)) << 4) + half * 8);
            *(uint2*)(smem + SM_XH + off) = make_uint2(h01, h23);
        }
        *(float4*)(smem + SM_SRED + (tm * 64 + f4 * 4) * 4) = s4;
    }
    __syncthreads();

    // ---- own s[f] over 256 rows; push to peer's SPEER before cluster sync ----
    if (t < 64) {
        float v = 0.f;
        #pragma unroll
        for (int r = 0; r < 16; r++)
            v += *(const float*)(smem + SM_SRED + (r * 64 + t) * 4);
        *(float*)(smem + SM_SPART + t * 4) = v;
        uint32_t rem;
        asm("mapa.shared::cluster.u32 %0, %1, %2;"
            : "=r"(rem) : "r"(sb + SM_SPEER + t * 4), "r"(rank ^ 1));
        asm volatile("st.shared::cluster.f32 [%0], %1;" :: "r"(rem), "f"(v) : "memory");
    }
    asm volatile("barrier.cluster.arrive.aligned;" ::: "memory");
    asm volatile("barrier.cluster.wait.aligned;" ::: "memory");

    // ---- pooled[o] = sum_f (s_own[f]+s_peer[f]) * gam[f,o] ----
    if (t < 128) {
        float p = 0.f;
        #pragma unroll 8
        for (int f = 0; f < 64; f++) {
            const float sf = *(const float*)(smem + SM_SPART + f * 4)
                           + *(const float*)(smem + SM_SPEER + f * 4);
            p += sf * gam[f * Ov + t];
        }
        *(float*)(smem + SM_POOL + t * 4) = p;
    }
    __syncthreads();

    // ---- MMA: warp w owns local rows 32w..32w+31; 2 mh x 2 nh sub-tiles ----
    const int am = lane & 15, acs = lane >> 4, asw = am & 7;
    const int bo = (lane & 7) | ((lane & 16) >> 1);
    const int bcs = (lane >> 3) & 1, bsw = bo & 7;
    const float* poolp = (const float*)(smem + SM_POOL);
    float* outb = out + ((size_t)b * Mv + rank * 256) * Ov;

    #pragma unroll 1
    for (int mh = 0; mh < 2; mh++) {
        const int mloc = 32 * w + 16 * mh;

        uint32_t afr[4][4];
        #pragma unroll
        for (int k = 0; k < 4; k++)
            ldsm4(sb + SM_XH + (uint32_t)((mloc + am) * 128
                  + ((((k << 1) | acs) ^ asw) << 4)), afr[k]);

        #pragma unroll 1
        for (int nh = 0; nh < 2; nh++) {
            const int o0 = nh * 64;
            float acc[8][4];
            #pragma unroll
            for (int j = 0; j < 8; j++)
                #pragma unroll
                for (int c = 0; c < 4; c++)
                    acc[j][c] = 0.f;

            #pragma unroll
            for (int k = 0; k < 4; k++)
                #pragma unroll
                for (int np = 0; np < 4; np++) {
                    uint32_t bf[4];
                    ldsm4(sb + SM_LN + (uint32_t)((o0 + np * 16 + bo) * 128
                            + ((((k << 1) | bcs) ^ bsw) << 4)), bf);
                    hmma(acc[2 * np],     afr[k], bf);
                    hmma(acc[2 * np + 1], afr[k], bf + 2);
                }

            #pragma unroll
            for (int np = 0; np < 4; np++) {
                const int col = o0 + np * 16 + 4 * tg;
                const float4 pl = *(const float4*)&poolp[col];
                const float* a0 = acc[2 * np];
                const float* a1 = acc[2 * np + 1];
                float* r0 = outb + (size_t)(mloc + g) * Ov + col;
                stg_cs4(r0,
                        fmaxf(a0[0] - pl.x, 0.f), fmaxf(a0[1] - pl.y, 0.f),
                        fmaxf(a1[0] - pl.z, 0.f), fmaxf(a1[1] - pl.w, 0.f));
                stg_cs4(r0 + 8 * Ov,
                        fmaxf(a0[2] - pl.x, 0.f), fmaxf(a0[3] - pl.y, 0.f),
                        fmaxf(a1[2] - pl.z, 0.f), fmaxf(a1[3] - pl.w, 0.f));
            }
        }
    }
}

extern "C" void kernel_launch(void* const* d_in, const int* in_sizes, int n_in,
                              void* d_out, int out_size)
{
    (void)in_sizes; (void)n_in; (void)out_size;
    const float* x   = (const float*)d_in[0];
    const float* lam = (const float*)d_in[1];
    const float* gam = (const float*)d_in[2];
    float* out = (float*)d_out;

    cudaFuncSetAttribute(eq_mma6_kernel, cudaFuncAttributeMaxDynamicSharedMemorySize,
                         SMEM_BYTES);
    eq_mma6_kernel<<<Bv * 2, 256, SMEM_BYTES>>>(x, lam, gam, out);
}